// round 3
// baseline (speedup 1.0000x reference)
#include <cuda_runtime.h>
#include <cuda_bf16.h>
#include <cstdint>
#include <cstddef>

// out[256,11008] = x[256,4096] @ W[11008,4096]^T * scale + bias, W ternary i32.
// Base-ISA only (harness compiles PTX at .target sm_100, no 'a' features):
// bf16 mma.sync m16n8k16, hi/lo split of x accumulated into one fp32 accum.
// BM=128 BN=160 BK=32, 512 threads, 138 CTAs (single wave), 2-stage cp.async.

#define M_TOK   256
#define K_DIM   4096
#define N_DIM   11008
#define BM      128
#define BN      160
#define BK      32
#define KITERS  (K_DIM / BK)          // 128
#define THREADS 512
#define N_TILES 69                    // 69*160 = 11040 >= 11008
#define GRID    (2 * N_TILES)         // 138

// --- stage layout (bytes). Rows padded to 80B for conflict-free ldmatrix ---
#define A_HI     0                    // 128 rows x 80B = 10240
#define A_LO     10240                // 128 rows x 80B
#define B_BF     20480                // 160 rows x 80B = 12800
#define W_INT    33280                // 160 rows x 128B = 20480
#define STAGE_BYTES 53760
#define SMEM_ALLOC (2 * STAGE_BYTES)  // 107520

__device__ __nv_bfloat16 g_xhi[M_TOK * K_DIM];
__device__ __nv_bfloat16 g_xlo[M_TOK * K_DIM];

// ---------------- asm helpers ----------------
__device__ __forceinline__ uint32_t smem_u32(const void* p) {
    uint32_t a;
    asm("{ .reg .u64 t; cvta.to.shared.u64 t, %1; cvt.u32.u64 %0, t; }"
        : "=r"(a) : "l"(p));
    return a;
}
__device__ __forceinline__ void cp16(uint32_t dst, const void* src) {
    asm volatile("cp.async.cg.shared.global [%0], [%1], 16;"
        :: "r"(dst), "l"(src) : "memory");
}
#define CP_COMMIT() asm volatile("cp.async.commit_group;" ::: "memory")
#define CP_WAIT1()  asm volatile("cp.async.wait_group 1;" ::: "memory")

__device__ __forceinline__ void ldsm4(uint32_t* r, uint32_t addr) {
    asm volatile("ldmatrix.sync.aligned.m8n8.x4.shared.b16 {%0,%1,%2,%3}, [%4];"
        : "=r"(r[0]), "=r"(r[1]), "=r"(r[2]), "=r"(r[3]) : "r"(addr));
}
__device__ __forceinline__ void ldsm2(uint32_t* r, uint32_t addr) {
    asm volatile("ldmatrix.sync.aligned.m8n8.x2.shared.b16 {%0,%1}, [%2];"
        : "=r"(r[0]), "=r"(r[1]) : "r"(addr));
}
__device__ __forceinline__ void mma_bf16(float* c, const uint32_t* a,
                                         const uint32_t* b) {
    asm volatile(
        "mma.sync.aligned.m16n8k16.row.col.f32.bf16.bf16.f32 "
        "{%0,%1,%2,%3}, {%4,%5,%6,%7}, {%8,%9}, {%0,%1,%2,%3};"
        : "+f"(c[0]), "+f"(c[1]), "+f"(c[2]), "+f"(c[3])
        : "r"(a[0]), "r"(a[1]), "r"(a[2]), "r"(a[3]), "r"(b[0]), "r"(b[1]));
}

// ternary int pair -> packed bf16x2 {0, +-1}; branch-free, never NaN
__device__ __forceinline__ uint32_t w2bf(int w0, int w1) {
    uint32_t l = (w0 == 0) ? 0u : ((w0 > 0) ? 0x3F80u : 0xBF80u);
    uint32_t h = (w1 == 0) ? 0u : ((w1 > 0) ? 0x3F80u : 0xBF80u);
    return l | (h << 16);
}

// ---------------- x split pre-kernel ----------------
__global__ void split_x_kernel(const float* __restrict__ x) {
    int i = (blockIdx.x * blockDim.x + threadIdx.x) << 2;
    float4 v = *reinterpret_cast<const float4*>(x + i);
    __nv_bfloat16 h0 = __float2bfloat16(v.x), h1 = __float2bfloat16(v.y);
    __nv_bfloat16 h2 = __float2bfloat16(v.z), h3 = __float2bfloat16(v.w);
    float r0 = v.x - __bfloat162float(h0), r1 = v.y - __bfloat162float(h1);
    float r2 = v.z - __bfloat162float(h2), r3 = v.w - __bfloat162float(h3);
    __nv_bfloat162* ph = reinterpret_cast<__nv_bfloat162*>(g_xhi + i);
    __nv_bfloat162* pl = reinterpret_cast<__nv_bfloat162*>(g_xlo + i);
    ph[0] = __halves2bfloat162(h0, h1); ph[1] = __halves2bfloat162(h2, h3);
    pl[0] = __floats2bfloat162_rn(r0, r1); pl[1] = __floats2bfloat162_rn(r2, r3);
}

// ---------------- main GEMM ----------------
__global__ void __launch_bounds__(THREADS, 1)
bitnet_gemm_kernel(const int* __restrict__ qw, const float* __restrict__ scale,
                   const float* __restrict__ bias, float* __restrict__ out) {
    extern __shared__ char smem[];
    const uint32_t su = smem_u32(smem);

    const int tid = threadIdx.x, wid = tid >> 5, lane = tid & 31;
    const int n_idx = blockIdx.x >> 1, m_idx = blockIdx.x & 1;
    const int n0 = n_idx * BN, m0 = m_idx * BM;
    const int n_sz = (n_idx == N_TILES - 1) ? (N_DIM - n0) : BN;   // 160 or 128

    const int warp_m = wid & 3;        // 4 m-warps, 32 rows each
    const int warp_n = wid >> 2;       // 4 n-warps, 40 cols each
    const int nbase = warp_n * 40;
    int ntiles = (n_sz - nbase) >> 3;
    if (ntiles > 5) ntiles = 5;
    if (ntiles < 0) ntiles = 0;

    // per-thread ldmatrix base offsets
    const uint32_t a_off = (uint32_t)((warp_m * 32 + (lane & 15)) * 80 +
                                      ((lane >> 4) << 4));
    const uint32_t b_off = (uint32_t)((nbase + (lane & 7)) * 80 +
                                      (((lane >> 3) & 1) << 4));

    // cp.async A assignment: thread t -> hi chunk t, lo chunk t (512 chunks ea)
    const int a_row = tid >> 2, a_kc = tid & 3;
    const __nv_bfloat16* ghi = g_xhi + (size_t)(m0 + a_row) * K_DIM + a_kc * 8;
    const __nv_bfloat16* glo = g_xlo + (size_t)(m0 + a_row) * K_DIM + a_kc * 8;
    const uint32_t a_dst = (uint32_t)(a_row * 80 + a_kc * 16);

    float acc[2][5][4];
#pragma unroll
    for (int mt = 0; mt < 2; ++mt)
#pragma unroll
        for (int nt = 0; nt < 5; ++nt)
#pragma unroll
            for (int r = 0; r < 4; ++r) acc[mt][nt][r] = 0.0f;

    // ---- stage loader (cp.async) ----
    auto load_stage = [&](int s, int k0) {
        const uint32_t st = su + (uint32_t)(s * STAGE_BYTES);
        cp16(st + A_HI + a_dst, ghi + k0);
        cp16(st + A_LO + a_dst, glo + k0);
        const int nchunks = n_sz * 8;          // 16B chunks of W int32
        for (int ci = tid; ci < nchunks; ci += THREADS) {
            int row = ci >> 3, kc = ci & 7;
            cp16(st + W_INT + (uint32_t)(row * 128 + kc * 16),
                 qw + (size_t)(n0 + row) * K_DIM + k0 + kc * 4);
        }
    };

    load_stage(0, 0);
    CP_COMMIT();

    for (int it = 0; it < KITERS; ++it) {
        const int cur = it & 1;
        const uint32_t st = su + (uint32_t)(cur * STAGE_BYTES);

        if (it + 1 < KITERS) load_stage(cur ^ 1, (it + 1) * BK);
        CP_COMMIT();
        CP_WAIT1();                           // stage `it` landed (own chunks)

        // convert exactly the W chunks THIS thread cp.async'd (no barrier yet)
        {
            const int nchunks = n_sz * 8;
            for (int ci = tid; ci < nchunks; ci += THREADS) {
                int row = ci >> 3, kc = ci & 7;
                uint32_t i0, i1, i2, i3;
                asm volatile("ld.shared.v4.u32 {%0,%1,%2,%3}, [%4];"
                    : "=r"(i0), "=r"(i1), "=r"(i2), "=r"(i3)
                    : "r"(st + W_INT + (uint32_t)(row * 128 + kc * 16)));
                uint32_t p0 = w2bf((int)i0, (int)i1);
                uint32_t p1 = w2bf((int)i2, (int)i3);
                asm volatile("st.shared.v2.b32 [%0], {%1,%2};"
                    :: "r"(st + B_BF + (uint32_t)(row * 80 + kc * 8)),
                       "r"(p0), "r"(p1) : "memory");
            }
        }
        __syncthreads();                      // all tiles visible to all warps

        // ---- compute BK=32: 2 k16 steps, hi+lo passes share accum ----
#pragma unroll
        for (int ks = 0; ks < 2; ++ks) {
            uint32_t b[5][2];
#pragma unroll
            for (int nt = 0; nt < 5; ++nt)
                if (nt < ntiles)
                    ldsm2(b[nt], st + B_BF + b_off +
                          (uint32_t)(nt * 8 * 80 + ks * 32));
            uint32_t a[2][4];
#pragma unroll
            for (int mt = 0; mt < 2; ++mt)
                ldsm4(a[mt], st + A_HI + a_off +
                      (uint32_t)(mt * 16 * 80 + ks * 32));
#pragma unroll
            for (int mt = 0; mt < 2; ++mt)
#pragma unroll
                for (int nt = 0; nt < 5; ++nt)
                    if (nt < ntiles) mma_bf16(acc[mt][nt], a[mt], b[nt]);
#pragma unroll
            for (int mt = 0; mt < 2; ++mt)
                ldsm4(a[mt], st + A_LO + a_off +
                      (uint32_t)(mt * 16 * 80 + ks * 32));
#pragma unroll
            for (int mt = 0; mt < 2; ++mt)
#pragma unroll
                for (int nt = 0; nt < 5; ++nt)
                    if (nt < ntiles) mma_bf16(acc[mt][nt], a[mt], b[nt]);
        }
        __syncthreads();                      // protect buffers for next loads
    }

    // ---- epilogue: scale/bias + store ----
    const int row_base = m0 + warp_m * 32 + (lane >> 2);
    const int col_base = n0 + nbase + ((lane & 3) << 1);
#pragma unroll
    for (int mt = 0; mt < 2; ++mt) {
#pragma unroll
        for (int nt = 0; nt < 5; ++nt) {
            if (nt < ntiles) {
                int col = col_base + nt * 8;
                float2 sc = *reinterpret_cast<const float2*>(scale + col);
                float2 bs = *reinterpret_cast<const float2*>(bias + col);
                int r0 = row_base + mt * 16;
                float2 o0, o1;
                o0.x = acc[mt][nt][0] * sc.x + bs.x;
                o0.y = acc[mt][nt][1] * sc.y + bs.y;
                o1.x = acc[mt][nt][2] * sc.x + bs.x;
                o1.y = acc[mt][nt][3] * sc.y + bs.y;
                *reinterpret_cast<float2*>(out + (size_t)r0 * N_DIM + col) = o0;
                *reinterpret_cast<float2*>(out + (size_t)(r0 + 8) * N_DIM + col) = o1;
            }
        }
    }
}

// ---------------- launch ----------------
extern "C" void kernel_launch(void* const* d_in, const int* in_sizes, int n_in,
                              void* d_out, int out_size) {
    const float* x = nullptr; const int* qw = nullptr;
    const float* scale = nullptr; const float* bias = nullptr;
    for (int i = 0; i < n_in; ++i) {
        if (in_sizes[i] == M_TOK * K_DIM) x = (const float*)d_in[i];
        else if (in_sizes[i] == N_DIM * K_DIM) qw = (const int*)d_in[i];
        else if (in_sizes[i] == N_DIM) {
            if (!scale) scale = (const float*)d_in[i];
            else bias = (const float*)d_in[i];
        }
    }
    float* out = (float*)d_out;

    cudaFuncSetAttribute(bitnet_gemm_kernel,
                         cudaFuncAttributeMaxDynamicSharedMemorySize, SMEM_ALLOC);

    split_x_kernel<<<(M_TOK * K_DIM) / (256 * 4), 256>>>(x);
    bitnet_gemm_kernel<<<GRID, THREADS, SMEM_ALLOC>>>(qw, scale, bias, out);
}

// round 4
// speedup vs baseline: 1.3467x; 1.3467x over previous
#include <cuda_runtime.h>
#include <cuda_bf16.h>
#include <cstdint>
#include <cstddef>

// out[256,11008] = x[256,4096] @ W[11008,4096]^T * scale + bias, W ternary i32.
// bf16 mma.sync m16n8k16, hi/lo split of x, fp32 accum (exact fp32 recovery).
// BM=128 BN=160 BK=64, 512 threads, 138 CTAs (single wave).
// W: LDG.128 int32 -> register ternary->bf16 convert -> STS.64 (no int SMEM
// stage, no convert pass). A: cp.async bf16 hi/lo. One __syncthreads per iter,
// 2 SMEM stages, prefetch distance covers full compute phase.

#define M_TOK   256
#define K_DIM   4096
#define N_DIM   11008
#define BM      128
#define BN      160
#define BK      64
#define KITERS  (K_DIM / BK)          // 64
#define THREADS 512
#define N_TILES 69                    // 69*160 = 11040 >= 11008
#define GRID    (2 * N_TILES)         // 138

// --- stage layout (bytes); rows padded to 144B (16B-aligned, +4 banks/row
//     => conflict-free ldmatrix with 128B of K data per row) ---
#define ROWB     144
#define A_HI     0                    // 128 rows x 144B = 18432
#define A_LO     18432
#define B_OFF    36864                // 160 rows x 144B = 23040
#define STAGE_BYTES 59904
#define SMEM_ALLOC (2 * STAGE_BYTES)  // 119808

__device__ __nv_bfloat16 g_xhi[M_TOK * K_DIM];
__device__ __nv_bfloat16 g_xlo[M_TOK * K_DIM];

// ---------------- asm helpers ----------------
__device__ __forceinline__ uint32_t smem_u32(const void* p) {
    uint32_t a;
    asm("{ .reg .u64 t; cvta.to.shared.u64 t, %1; cvt.u32.u64 %0, t; }"
        : "=r"(a) : "l"(p));
    return a;
}
__device__ __forceinline__ void cp16(uint32_t dst, const void* src) {
    asm volatile("cp.async.cg.shared.global [%0], [%1], 16;"
        :: "r"(dst), "l"(src) : "memory");
}
#define CP_COMMIT() asm volatile("cp.async.commit_group;" ::: "memory")
#define CP_WAIT0()  asm volatile("cp.async.wait_group 0;" ::: "memory")

__device__ __forceinline__ void ldsm4(uint32_t* r, uint32_t addr) {
    asm volatile("ldmatrix.sync.aligned.m8n8.x4.shared.b16 {%0,%1,%2,%3}, [%4];"
        : "=r"(r[0]), "=r"(r[1]), "=r"(r[2]), "=r"(r[3]) : "r"(addr));
}
__device__ __forceinline__ void ldsm2(uint32_t* r, uint32_t addr) {
    asm volatile("ldmatrix.sync.aligned.m8n8.x2.shared.b16 {%0,%1}, [%2];"
        : "=r"(r[0]), "=r"(r[1]) : "r"(addr));
}
__device__ __forceinline__ void mma_bf16(float* c, const uint32_t* a,
                                         const uint32_t* b) {
    asm volatile(
        "mma.sync.aligned.m16n8k16.row.col.f32.bf16.bf16.f32 "
        "{%0,%1,%2,%3}, {%4,%5,%6,%7}, {%8,%9}, {%0,%1,%2,%3};"
        : "+f"(c[0]), "+f"(c[1]), "+f"(c[2]), "+f"(c[3])
        : "r"(a[0]), "r"(a[1]), "r"(a[2]), "r"(a[3]), "r"(b[0]), "r"(b[1]));
}
// ternary int pair -> packed bf16x2 {0,+-1}; branch-free, never NaN
__device__ __forceinline__ uint32_t w2bf(int w0, int w1) {
    uint32_t l = (w0 == 0) ? 0u : ((w0 > 0) ? 0x3F80u : 0xBF80u);
    uint32_t h = (w1 == 0) ? 0u : ((w1 > 0) ? 0x3F80u : 0xBF80u);
    return l | (h << 16);
}

// ---------------- x split pre-kernel ----------------
__global__ void split_x_kernel(const float* __restrict__ x) {
    int i = (blockIdx.x * blockDim.x + threadIdx.x) << 2;
    float4 v = *reinterpret_cast<const float4*>(x + i);
    __nv_bfloat16 h0 = __float2bfloat16(v.x), h1 = __float2bfloat16(v.y);
    __nv_bfloat16 h2 = __float2bfloat16(v.z), h3 = __float2bfloat16(v.w);
    float r0 = v.x - __bfloat162float(h0), r1 = v.y - __bfloat162float(h1);
    float r2 = v.z - __bfloat162float(h2), r3 = v.w - __bfloat162float(h3);
    __nv_bfloat162* ph = reinterpret_cast<__nv_bfloat162*>(g_xhi + i);
    __nv_bfloat162* pl = reinterpret_cast<__nv_bfloat162*>(g_xlo + i);
    ph[0] = __halves2bfloat162(h0, h1); ph[1] = __halves2bfloat162(h2, h3);
    pl[0] = __floats2bfloat162_rn(r0, r1); pl[1] = __floats2bfloat162_rn(r2, r3);
}

// ---------------- main GEMM ----------------
__global__ void __launch_bounds__(THREADS, 1)
bitnet_gemm_kernel(const int* __restrict__ qw, const float* __restrict__ scale,
                   const float* __restrict__ bias, float* __restrict__ out) {
    extern __shared__ char smem[];
    const uint32_t su = smem_u32(smem);

    const int tid = threadIdx.x, wid = tid >> 5, lane = tid & 31;
    const int n_idx = blockIdx.x >> 1, m_idx = blockIdx.x & 1;
    const int n0 = n_idx * BN, m0 = m_idx * BM;
    const int n_sz = (n_idx == N_TILES - 1) ? (N_DIM - n0) : BN;   // 160 or 128

    const int warp_m = wid & 3;        // 4 m-warps, 32 rows each
    const int warp_n = wid >> 2;       // 4 n-warps, 40 cols each
    const int nbase = warp_n * 40;
    int ntiles = (n_sz - nbase) >> 3;
    if (ntiles > 5) ntiles = 5;
    if (ntiles < 0) ntiles = 0;

    // ldmatrix per-thread offsets (row stride 144B)
    const uint32_t a_off = (uint32_t)((warp_m * 32 + (lane & 15)) * ROWB +
                                      ((lane >> 4) << 4));
    const uint32_t b_off = (uint32_t)((nbase + (lane & 7)) * ROWB +
                                      (((lane >> 3) & 1) << 4));

    // W LDG assignment: 2560 16B-chunks (160 rows x 16), 5 per thread
    int w_row[5]; const int* w_src[5];
#pragma unroll
    for (int j = 0; j < 5; ++j) {
        int c = tid + 512 * j;
        int row = c >> 4, kc = c & 15;
        w_row[j] = row;
        int srow = (row < n_sz) ? row : 0;     // clamp (data unread if OOB)
        w_src[j] = qw + (size_t)(n0 + srow) * K_DIM + kc * 4;
    }
    // A cp.async assignment: per split 1024 chunks (128 rows x 8), 2 per thread
    const int a_r0 = tid >> 3, a_k0 = tid & 7;          // chunk tid
    const int a_r1 = (tid + 512) >> 3, a_k1 = tid & 7;  // chunk tid+512
    const __nv_bfloat16* ghi0 = g_xhi + (size_t)(m0 + a_r0) * K_DIM + a_k0 * 8;
    const __nv_bfloat16* ghi1 = g_xhi + (size_t)(m0 + a_r1) * K_DIM + a_k1 * 8;
    const __nv_bfloat16* glo0 = g_xlo + (size_t)(m0 + a_r0) * K_DIM + a_k0 * 8;
    const __nv_bfloat16* glo1 = g_xlo + (size_t)(m0 + a_r1) * K_DIM + a_k1 * 8;
    const uint32_t ad0 = (uint32_t)(a_r0 * ROWB + a_k0 * 16);
    const uint32_t ad1 = (uint32_t)(a_r1 * ROWB + a_k1 * 16);

    float acc[2][5][4];
#pragma unroll
    for (int mt = 0; mt < 2; ++mt)
#pragma unroll
        for (int nt = 0; nt < 5; ++nt)
#pragma unroll
            for (int r = 0; r < 4; ++r) acc[mt][nt][r] = 0.0f;

    int wreg[20];

    auto ldgW = [&](int k0) {
#pragma unroll
        for (int j = 0; j < 5; ++j) {
            asm volatile("ld.global.cs.v4.u32 {%0,%1,%2,%3}, [%4];"
                : "=r"(*(uint32_t*)&wreg[4*j]),   "=r"(*(uint32_t*)&wreg[4*j+1]),
                  "=r"(*(uint32_t*)&wreg[4*j+2]), "=r"(*(uint32_t*)&wreg[4*j+3])
                : "l"(w_src[j] + k0));
        }
    };
    auto cpA = [&](int s, int k0) {
        const uint32_t st = su + (uint32_t)(s * STAGE_BYTES);
        cp16(st + A_HI + ad0, ghi0 + k0);
        cp16(st + A_HI + ad1, ghi1 + k0);
        cp16(st + A_LO + ad0, glo0 + k0);
        cp16(st + A_LO + ad1, glo1 + k0);
    };

    // ---- prologue ----
    ldgW(0);
    cpA(0, 0);
    CP_COMMIT();

#pragma unroll 1
    for (int it = 0; it < KITERS; ++it) {
        const int cur = it & 1;
        const uint32_t st = su + (uint32_t)(cur * STAGE_BYTES);

        // STS W(it) from regs (ternary -> bf16)
#pragma unroll
        for (int j = 0; j < 5; ++j) {
            int c = tid + 512 * j, kc = c & 15;
            uint32_t p0 = w2bf(wreg[4*j],   wreg[4*j+1]);
            uint32_t p1 = w2bf(wreg[4*j+2], wreg[4*j+3]);
            asm volatile("st.shared.v2.b32 [%0], {%1,%2};"
                :: "r"(st + B_OFF + (uint32_t)(w_row[j] * ROWB + kc * 8)),
                   "r"(p0), "r"(p1) : "memory");
        }
        if (it + 1 < KITERS) ldgW((it + 1) * BK);   // latency covered by compute
        CP_WAIT0();                                 // A(it) landed
        __syncthreads();
        if (it + 1 < KITERS) { cpA(cur ^ 1, (it + 1) * BK); CP_COMMIT(); }

        // ---- compute BK=64: 4 k16 steps, hi+lo share accum ----
#pragma unroll
        for (int ks = 0; ks < 4; ++ks) {
            const uint32_t ksb = (uint32_t)(ks * 32);
            uint32_t b[5][2];
#pragma unroll
            for (int nt = 0; nt < 5; ++nt)
                if (nt < ntiles)
                    ldsm2(b[nt], st + B_OFF + b_off +
                          (uint32_t)(nt * 8 * ROWB) + ksb);
            uint32_t a[2][4];
#pragma unroll
            for (int mt = 0; mt < 2; ++mt)
                ldsm4(a[mt], st + A_HI + a_off + (uint32_t)(mt * 16 * ROWB) + ksb);
#pragma unroll
            for (int mt = 0; mt < 2; ++mt)
#pragma unroll
                for (int nt = 0; nt < 5; ++nt)
                    if (nt < ntiles) mma_bf16(acc[mt][nt], a[mt], b[nt]);
#pragma unroll
            for (int mt = 0; mt < 2; ++mt)
                ldsm4(a[mt], st + A_LO + a_off + (uint32_t)(mt * 16 * ROWB) + ksb);
#pragma unroll
            for (int mt = 0; mt < 2; ++mt)
#pragma unroll
                for (int nt = 0; nt < 5; ++nt)
                    if (nt < ntiles) mma_bf16(acc[mt][nt], a[mt], b[nt]);
        }
        // no second sync: next STS_W/cpA target the other buffer, and the
        // barrier above already ordered compute(it-1) before them.
    }

    // ---- epilogue: scale/bias + store ----
    const int row_base = m0 + warp_m * 32 + (lane >> 2);
    const int col_base = n0 + nbase + ((lane & 3) << 1);
#pragma unroll
    for (int mt = 0; mt < 2; ++mt) {
#pragma unroll
        for (int nt = 0; nt < 5; ++nt) {
            if (nt < ntiles) {
                int col = col_base + nt * 8;
                float2 sc = *reinterpret_cast<const float2*>(scale + col);
                float2 bs = *reinterpret_cast<const float2*>(bias + col);
                int r0 = row_base + mt * 16;
                float2 o0, o1;
                o0.x = acc[mt][nt][0] * sc.x + bs.x;
                o0.y = acc[mt][nt][1] * sc.y + bs.y;
                o1.x = acc[mt][nt][2] * sc.x + bs.x;
                o1.y = acc[mt][nt][3] * sc.y + bs.y;
                *reinterpret_cast<float2*>(out + (size_t)r0 * N_DIM + col) = o0;
                *reinterpret_cast<float2*>(out + (size_t)(r0 + 8) * N_DIM + col) = o1;
            }
        }
    }
}

// ---------------- launch ----------------
extern "C" void kernel_launch(void* const* d_in, const int* in_sizes, int n_in,
                              void* d_out, int out_size) {
    const float* x = nullptr; const int* qw = nullptr;
    const float* scale = nullptr; const float* bias = nullptr;
    for (int i = 0; i < n_in; ++i) {
        if (in_sizes[i] == M_TOK * K_DIM) x = (const float*)d_in[i];
        else if (in_sizes[i] == N_DIM * K_DIM) qw = (const int*)d_in[i];
        else if (in_sizes[i] == N_DIM) {
            if (!scale) scale = (const float*)d_in[i];
            else bias = (const float*)d_in[i];
        }
    }
    float* out = (float*)d_out;

    cudaFuncSetAttribute(bitnet_gemm_kernel,
                         cudaFuncAttributeMaxDynamicSharedMemorySize, SMEM_ALLOC);

    split_x_kernel<<<(M_TOK * K_DIM) / (256 * 4), 256>>>(x);
    bitnet_gemm_kernel<<<GRID, THREADS, SMEM_ALLOC>>>(qw, scale, bias, out);
}

// round 5
// speedup vs baseline: 2.0015x; 1.4862x over previous
#include <cuda_runtime.h>
#include <cuda_fp16.h>
#include <cstdint>
#include <cstddef>

// out[256,11008] = x[256,4096] @ W[11008,4096]^T * scale + bias, W ternary i32.
// fp16 mma.sync m16n8k16 single pass (x rounded to fp16; products with
// {-1,0,1} exact; fp32 accum => rel_err ~1.4e-4 << 1e-3).
// BM=128 BN=160 BK=64, 512 threads, 138 CTAs (single wave).
// W: LDG.128 int32 -> register ternary->fp16 convert -> STS.64.
// A: cp.async fp16. One __syncthreads per iter, 2 SMEM stages.

#define M_TOK   256
#define K_DIM   4096
#define N_DIM   11008
#define BM      128
#define BN      160
#define BK      64
#define KITERS  (K_DIM / BK)          // 64
#define THREADS 512
#define N_TILES 69                    // 69*160 = 11040 >= 11008
#define GRID    (2 * N_TILES)         // 138

// rows padded to 144B (16B-aligned, +4 banks/row => conflict-free ldmatrix)
#define ROWB     144
#define A_OFF    0                    // 128 rows x 144B = 18432
#define B_OFF    18432                // 160 rows x 144B = 23040
#define STAGE_BYTES 41472
#define SMEM_ALLOC (2 * STAGE_BYTES)  // 82944

__device__ __half g_xh[M_TOK * K_DIM];

// ---------------- asm helpers ----------------
__device__ __forceinline__ uint32_t smem_u32(const void* p) {
    uint32_t a;
    asm("{ .reg .u64 t; cvta.to.shared.u64 t, %1; cvt.u32.u64 %0, t; }"
        : "=r"(a) : "l"(p));
    return a;
}
__device__ __forceinline__ void cp16(uint32_t dst, const void* src) {
    asm volatile("cp.async.cg.shared.global [%0], [%1], 16;"
        :: "r"(dst), "l"(src) : "memory");
}
#define CP_COMMIT() asm volatile("cp.async.commit_group;" ::: "memory")
#define CP_WAIT0()  asm volatile("cp.async.wait_group 0;" ::: "memory")

__device__ __forceinline__ void ldsm4(uint32_t* r, uint32_t addr) {
    asm volatile("ldmatrix.sync.aligned.m8n8.x4.shared.b16 {%0,%1,%2,%3}, [%4];"
        : "=r"(r[0]), "=r"(r[1]), "=r"(r[2]), "=r"(r[3]) : "r"(addr));
}
__device__ __forceinline__ void ldsm2(uint32_t* r, uint32_t addr) {
    asm volatile("ldmatrix.sync.aligned.m8n8.x2.shared.b16 {%0,%1}, [%2];"
        : "=r"(r[0]), "=r"(r[1]) : "r"(addr));
}
__device__ __forceinline__ void mma_f16(float* c, const uint32_t* a,
                                        const uint32_t* b) {
    asm volatile(
        "mma.sync.aligned.m16n8k16.row.col.f32.f16.f16.f32 "
        "{%0,%1,%2,%3}, {%4,%5,%6,%7}, {%8,%9}, {%0,%1,%2,%3};"
        : "+f"(c[0]), "+f"(c[1]), "+f"(c[2]), "+f"(c[3])
        : "r"(a[0]), "r"(a[1]), "r"(a[2]), "r"(a[3]), "r"(b[0]), "r"(b[1]));
}
// ternary int pair -> packed fp16x2 {0,+-1}; fp16 1.0 = 0x3C00
__device__ __forceinline__ uint32_t w2h(int w0, int w1) {
    uint32_t l = (w0 == 0) ? 0u : ((w0 > 0) ? 0x3C00u : 0xBC00u);
    uint32_t h = (w1 == 0) ? 0u : ((w1 > 0) ? 0x3C00u : 0xBC00u);
    return l | (h << 16);
}

// ---------------- x convert pre-kernel ----------------
__global__ void conv_x_kernel(const float* __restrict__ x) {
    int i = (blockIdx.x * blockDim.x + threadIdx.x) << 2;
    float4 v = *reinterpret_cast<const float4*>(x + i);
    __half2* ph = reinterpret_cast<__half2*>(g_xh + i);
    ph[0] = __floats2half2_rn(v.x, v.y);
    ph[1] = __floats2half2_rn(v.z, v.w);
}

// ---------------- main GEMM ----------------
__global__ void __launch_bounds__(THREADS, 1)
bitnet_gemm_kernel(const int* __restrict__ qw, const float* __restrict__ scale,
                   const float* __restrict__ bias, float* __restrict__ out) {
    extern __shared__ char smem[];
    const uint32_t su = smem_u32(smem);

    const int tid = threadIdx.x, wid = tid >> 5, lane = tid & 31;
    const int n_idx = blockIdx.x >> 1, m_idx = blockIdx.x & 1;
    const int n0 = n_idx * BN, m0 = m_idx * BM;
    const int n_sz = (n_idx == N_TILES - 1) ? (N_DIM - n0) : BN;   // 160 or 128

    const int warp_m = wid & 3;        // 4 m-warps, 32 rows each
    const int warp_n = wid >> 2;       // 4 n-warps, 40 cols each
    const int nbase = warp_n * 40;
    int ntiles = (n_sz - nbase) >> 3;
    if (ntiles > 5) ntiles = 5;
    if (ntiles < 0) ntiles = 0;

    // ldmatrix per-thread offsets (row stride 144B)
    const uint32_t a_off = (uint32_t)((warp_m * 32 + (lane & 15)) * ROWB +
                                      ((lane >> 4) << 4));
    const uint32_t b_off = (uint32_t)((nbase + (lane & 7)) * ROWB +
                                      (((lane >> 3) & 1) << 4));

    // W LDG assignment: 2560 16B-chunks (160 rows x 16), 5 per thread
    int w_row[5]; const int* w_src[5];
#pragma unroll
    for (int j = 0; j < 5; ++j) {
        int c = tid + 512 * j;
        int row = c >> 4, kc = c & 15;
        w_row[j] = row;
        int srow = (row < n_sz) ? row : 0;     // clamp (data unread if OOB)
        w_src[j] = qw + (size_t)(n0 + srow) * K_DIM + kc * 4;
    }
    // A cp.async assignment: 1024 chunks (128 rows x 8 x 16B), 2 per thread
    const int a_r0 = tid >> 3, a_k0 = tid & 7;
    const int a_r1 = (tid + 512) >> 3, a_k1 = tid & 7;
    const __half* gx0 = g_xh + (size_t)(m0 + a_r0) * K_DIM + a_k0 * 8;
    const __half* gx1 = g_xh + (size_t)(m0 + a_r1) * K_DIM + a_k1 * 8;
    const uint32_t ad0 = (uint32_t)(a_r0 * ROWB + a_k0 * 16);
    const uint32_t ad1 = (uint32_t)(a_r1 * ROWB + a_k1 * 16);

    float acc[2][5][4];
#pragma unroll
    for (int mt = 0; mt < 2; ++mt)
#pragma unroll
        for (int nt = 0; nt < 5; ++nt)
#pragma unroll
            for (int r = 0; r < 4; ++r) acc[mt][nt][r] = 0.0f;

    int wreg[20];

    auto ldgW = [&](int k0) {
#pragma unroll
        for (int j = 0; j < 5; ++j) {
            asm volatile("ld.global.cs.v4.u32 {%0,%1,%2,%3}, [%4];"
                : "=r"(*(uint32_t*)&wreg[4*j]),   "=r"(*(uint32_t*)&wreg[4*j+1]),
                  "=r"(*(uint32_t*)&wreg[4*j+2]), "=r"(*(uint32_t*)&wreg[4*j+3])
                : "l"(w_src[j] + k0));
        }
    };
    auto cpA = [&](int s, int k0) {
        const uint32_t st = su + (uint32_t)(s * STAGE_BYTES);
        cp16(st + A_OFF + ad0, gx0 + k0);
        cp16(st + A_OFF + ad1, gx1 + k0);
    };

    // ---- prologue ----
    ldgW(0);
    cpA(0, 0);
    CP_COMMIT();

#pragma unroll 1
    for (int it = 0; it < KITERS; ++it) {
        const int cur = it & 1;
        const uint32_t st = su + (uint32_t)(cur * STAGE_BYTES);

        // STS W(it) from regs (ternary -> fp16)
#pragma unroll
        for (int j = 0; j < 5; ++j) {
            int c = tid + 512 * j, kc = c & 15;
            uint32_t p0 = w2h(wreg[4*j],   wreg[4*j+1]);
            uint32_t p1 = w2h(wreg[4*j+2], wreg[4*j+3]);
            asm volatile("st.shared.v2.b32 [%0], {%1,%2};"
                :: "r"(st + B_OFF + (uint32_t)(w_row[j] * ROWB + kc * 8)),
                   "r"(p0), "r"(p1) : "memory");
        }
        if (it + 1 < KITERS) ldgW((it + 1) * BK);   // consumed next iter top
        CP_WAIT0();                                 // A(it) landed
        __syncthreads();
        if (it + 1 < KITERS) { cpA(cur ^ 1, (it + 1) * BK); CP_COMMIT(); }

        // ---- compute BK=64: 4 k16 steps, single fp16 pass ----
#pragma unroll
        for (int ks = 0; ks < 4; ++ks) {
            const uint32_t ksb = (uint32_t)(ks * 32);
            uint32_t b[5][2];
#pragma unroll
            for (int nt = 0; nt < 5; ++nt)
                if (nt < ntiles)
                    ldsm2(b[nt], st + B_OFF + b_off +
                          (uint32_t)(nt * 8 * ROWB) + ksb);
            uint32_t a[2][4];
#pragma unroll
            for (int mt = 0; mt < 2; ++mt)
                ldsm4(a[mt], st + A_OFF + a_off + (uint32_t)(mt * 16 * ROWB) + ksb);
#pragma unroll
            for (int mt = 0; mt < 2; ++mt)
#pragma unroll
                for (int nt = 0; nt < 5; ++nt)
                    if (nt < ntiles) mma_f16(acc[mt][nt], a[mt], b[nt]);
        }
        // single barrier per iter: next iter's STS/cpA hit the other buffer,
        // ordered against compute(it-1) by the barrier above.
    }

    // ---- epilogue: scale/bias + store ----
    const int row_base = m0 + warp_m * 32 + (lane >> 2);
    const int col_base = n0 + nbase + ((lane & 3) << 1);
#pragma unroll
    for (int mt = 0; mt < 2; ++mt) {
#pragma unroll
        for (int nt = 0; nt < 5; ++nt) {
            if (nt < ntiles) {
                int col = col_base + nt * 8;
                float2 sc = *reinterpret_cast<const float2*>(scale + col);
                float2 bs = *reinterpret_cast<const float2*>(bias + col);
                int r0 = row_base + mt * 16;
                float2 o0, o1;
                o0.x = acc[mt][nt][0] * sc.x + bs.x;
                o0.y = acc[mt][nt][1] * sc.y + bs.y;
                o1.x = acc[mt][nt][2] * sc.x + bs.x;
                o1.y = acc[mt][nt][3] * sc.y + bs.y;
                *reinterpret_cast<float2*>(out + (size_t)r0 * N_DIM + col) = o0;
                *reinterpret_cast<float2*>(out + (size_t)(r0 + 8) * N_DIM + col) = o1;
            }
        }
    }
}

// ---------------- launch ----------------
extern "C" void kernel_launch(void* const* d_in, const int* in_sizes, int n_in,
                              void* d_out, int out_size) {
    const float* x = nullptr; const int* qw = nullptr;
    const float* scale = nullptr; const float* bias = nullptr;
    for (int i = 0; i < n_in; ++i) {
        if (in_sizes[i] == M_TOK * K_DIM) x = (const float*)d_in[i];
        else if (in_sizes[i] == N_DIM * K_DIM) qw = (const int*)d_in[i];
        else if (in_sizes[i] == N_DIM) {
            if (!scale) scale = (const float*)d_in[i];
            else bias = (const float*)d_in[i];
        }
    }
    float* out = (float*)d_out;

    cudaFuncSetAttribute(bitnet_gemm_kernel,
                         cudaFuncAttributeMaxDynamicSharedMemorySize, SMEM_ALLOC);

    conv_x_kernel<<<(M_TOK * K_DIM) / (256 * 4), 256>>>(x);
    bitnet_gemm_kernel<<<GRID, THREADS, SMEM_ALLOC>>>(qw, scale, bias, out);
}